// round 8
// baseline (speedup 1.0000x reference)
#include <cuda_runtime.h>
#include <cuda_bf16.h>
#include <cstdint>

#define HH   256
#define WW   256
#define NP   (HH * WW)
#define NG   1024
#define MM   50
#define NCH  150
#define ROWF 160                // padded feature row: 4 quarters x 40 floats
#define QSTR 40                 // floats per quarter slot
#define QPAIR 19                // real f32x2 pairs per quarter
#define TPX  16
#define TPY  4
#define NTX  (WW / TPX)         // 16
#define NTY  (HH / TPY)         // 64
#define NTILES (NTX * NTY)      // 1024
#define TRB  75                 // transpose blocks (75*256*8 = 153600 = 150*1024)
#define CULLB (NTILES / 8)      // 128 cull blocks

// Scratch (device globals; no allocation allowed)
__device__ float g_params[NG * 8];                 // cx, cy, c1, c2, c3, op
__device__ __align__(16) float g_featT[NG * ROWF]; // [n][160] channel-major padded
__device__ short g_list[NTILES][NG];               // per-tile ordered lists
__device__ int   g_count[NTILES];

// ---------------------------------------------------------------------------
__device__ __forceinline__ void project(int n,
        const float* __restrict__ xyz, const float* __restrict__ chol,
        const float* __restrict__ opac,
        float& cx, float& cy, float& c1, float& c2, float& c3, float& op,
        float4& bb) {
    float2 xr = ((const float2*)xyz)[n];
    float x  = tanhf(xr.x);
    float y  = tanhf(xr.y);
    float l1 = chol[3 * n + 0] + 0.5f;
    float l2 = chol[3 * n + 1];
    float l3 = chol[3 * n + 2] + 0.5f;
    float a = l1 * l1;
    float b = l1 * l2;
    float c = l2 * l2 + l3 * l3;
    float det = a * c - b * b;
    c1 = c / det;
    c2 = -b / det;
    c3 = a / det;
    cx = 0.5f * ((x + 1.0f) * (float)WW - 1.0f);
    cy = 0.5f * ((y + 1.0f) * (float)HH - 1.0f);
    op = opac[n];
    // alpha >= 1/255 <=> sigma <= T = ln(255*op); ellipse extents + margin
    float T = __logf(255.0f * op);
    if (T > 0.0f) {
        float hx = sqrtf(2.0f * T * a) + 2.0f;
        float hy = sqrtf(2.0f * T * c) + 2.0f;
        bb = make_float4(cx - hx, cx + hx, cy - hy, cy + hy);
    } else {
        bb = make_float4(1e9f, -1e9f, 1e9f, -1e9f);
    }
}

// ---------------------------------------------------------------------------
// Kernel A: blocks [0,75)  feature transpose, 8 elems/thread (MLP=8);
//           blocks [75,203) project-in-SMEM + warp-per-tile cull;
//           cull block 0 also persists params + zeroes feature padding.
// ---------------------------------------------------------------------------
__global__ void prep_and_cull(const float* __restrict__ xyz,
                              const float* __restrict__ chol,
                              const float* __restrict__ opac,
                              const float* __restrict__ fdc,
                              const int*   __restrict__ cid_p) {
    const int tid = threadIdx.x;
    if (blockIdx.x < TRB) {
        const int cid = *cid_p;
#pragma unroll
        for (int k = 0; k < 8; k++) {
            int i = blockIdx.x * 2048 + k * 256 + tid;   // (t,n), n minor
            int t = i >> 10;                             // channel 0..149
            int n = i & (NG - 1);
            int m  = t / 3;
            int cc = t - 3 * m;
            float v = fdc[(((size_t)cid * MM + m) * NG + n) * 3 + cc];
            g_featT[n * ROWF + t + 2 * (t / 38)] = v;    // quarter-padded slot
        }
        return;
    }

    __shared__ __align__(16) float4 s_bb[NG];            // 16 KB
    const int cb = blockIdx.x - TRB;                     // 0..127
#pragma unroll
    for (int j = 0; j < 4; j++) {
        int n = tid + j * 256;
        float cx, cy, c1, c2, c3, op;
        float4 bb;
        project(n, xyz, chol, opac, cx, cy, c1, c2, c3, op, bb);
        s_bb[n] = bb;
        if (cb == 0) {
            float4* p = (float4*)&g_params[n * 8];
            p[0] = make_float4(cx, cy, c1, c2);
            p[1] = make_float4(c3, op, 0.0f, 0.0f);
            float* fr = &g_featT[n * ROWF];              // zero padding slots
            fr[38] = 0.f; fr[39] = 0.f; fr[78] = 0.f; fr[79] = 0.f;
            fr[118] = 0.f; fr[119] = 0.f;
            fr[156] = 0.f; fr[157] = 0.f; fr[158] = 0.f; fr[159] = 0.f;
        }
    }
    __syncthreads();

    const int lane = tid & 31;
    const int tile = cb * 8 + (tid >> 5);                // one warp per tile
    const float fxl = (float)((tile & (NTX - 1)) * TPX);
    const float fxh = fxl + (float)(TPX - 1);
    const float fyl = (float)((tile >> 4) * TPY);
    const float fyh = fyl + (float)(TPY - 1);
    int off = 0;
#pragma unroll 8
    for (int j = 0; j < NG / 32; j++) {
        int g = j * 32 + lane;
        float4 bb = s_bb[g];
        bool hit = (bb.x <= fxh) && (bb.y >= fxl) && (bb.z <= fyh) && (bb.w >= fyl);
        unsigned m = __ballot_sync(0xffffffffu, hit);
        if (hit) {
            int rank = __popc(m & ((1u << lane) - 1u));
            g_list[tile][off + rank] = (short)g;
        }
        off += __popc(m);
    }
    if (lane == 0) g_count[tile] = off;
}

// ---------------------------------------------------------------------------
// Kernel B: warp-autonomous render. One CTA per 16x4 tile, 4 threads/pixel
// (warp-uniform channel quarter -> all loads broadcast). No SMEM, no barriers.
// ---------------------------------------------------------------------------
__global__ __launch_bounds__(256, 3) void render(float* __restrict__ out) {
    const int tid  = threadIdx.x;
    const int tile = blockIdx.x;
    const int tx0  = (tile & (NTX - 1)) * TPX;
    const int ty0  = (tile >> 4) * TPY;

    const int  pix = tid & 63;              // 0..63
    const int  q   = tid >> 6;              // channel quarter, warp-uniform
    const float fx = (float)(tx0 + (pix & (TPX - 1)));
    const float fy = (float)(ty0 + (pix >> 4));

    const int count = g_count[tile];
    const short* __restrict__ list = g_list[tile];
    const float4* __restrict__ pp  = (const float4*)g_params;

    unsigned long long acc[QPAIR];
#pragma unroll
    for (int k = 0; k < QPAIR; k++) acc[k] = 0ull;

    for (int c0 = 0; c0 < count; c0 += 8) {
        uint4 l8 = *(const uint4*)(list + c0);           // 8 list entries
        unsigned v[4] = {l8.x, l8.y, l8.z, l8.w};
#pragma unroll
        for (int j = 0; j < 8; j++) {
            if (c0 + j < count) {
                int n = (int)((v[j >> 1] >> ((j & 1) * 16)) & 0xffffu);
                float4 P0 = pp[2 * n];
                float4 P1 = pp[2 * n + 1];
                float dx = P0.x - fx;
                float dy = P0.y - fy;
                float sig = 0.5f * (P0.z * dx * dx + P1.x * dy * dy) + P0.w * dx * dy;
                float al = fminf(0.999f, P1.y * __expf(-sig));
                al = (sig >= 0.0f && al >= (1.0f / 255.0f)) ? al : 0.0f;
                unsigned long long ap;
                asm("mov.b64 %0, {%1,%1};" : "=l"(ap) : "r"(__float_as_uint(al)));
                const float* rb = g_featT + n * ROWF + q * QSTR;  // 16B aligned
                const ulonglong2* f4 = (const ulonglong2*)rb;
#pragma unroll
                for (int k = 0; k < 9; k++) {            // pairs 0..17
                    ulonglong2 f2 = f4[k];
                    asm("fma.rn.f32x2 %0, %1, %2, %0;" : "+l"(acc[2*k])   : "l"(ap), "l"(f2.x));
                    asm("fma.rn.f32x2 %0, %1, %2, %0;" : "+l"(acc[2*k+1]) : "l"(ap), "l"(f2.y));
                }
                unsigned long long flast = ((const unsigned long long*)rb)[18];
                asm("fma.rn.f32x2 %0, %1, %2, %0;" : "+l"(acc[18]) : "l"(ap), "l"(flast));
            }
        }
    }

    // ---- epilogue: coalesced channel-plane stores ----
    const int pofs = (ty0 + (pix >> 4)) * WW + tx0 + (pix & (TPX - 1));
#pragma unroll
    for (int k = 0; k < QPAIR; k++) {
        int ch = 38 * q + 2 * k;
        if (ch < NCH) {                      // ch even; ch+1 <= 149 when valid
            unsigned lo, hi;
            asm("mov.b64 {%0,%1}, %2;" : "=r"(lo), "=r"(hi) : "l"(acc[k]));
            out[(size_t)ch       * NP + pofs] = __uint_as_float(lo);
            out[(size_t)(ch + 1) * NP + pofs] = __uint_as_float(hi);
        }
    }
}

// ---------------------------------------------------------------------------
extern "C" void kernel_launch(void* const* d_in, const int* in_sizes, int n_in,
                              void* d_out, int out_size) {
    const float* xyz  = (const float*)d_in[0];  // [N,2]
    const float* chol = (const float*)d_in[1];  // [N,3]
    const float* opac = (const float*)d_in[2];  // [N,1]
    const float* fdc  = (const float*)d_in[3];  // [K,M,N,3]
    const int*   cid  = (const int*)d_in[4];    // scalar

    prep_and_cull<<<TRB + CULLB, 256>>>(xyz, chol, opac, fdc, cid);
    render<<<NTILES, 256>>>((float*)d_out);
}

// round 9
// speedup vs baseline: 1.4885x; 1.4885x over previous
#include <cuda_runtime.h>
#include <cuda_bf16.h>
#include <cstdint>

#define HH   256
#define WW   256
#define NP   (HH * WW)
#define NG   1024
#define MM   50
#define NCH  150
#define NCHF 152                // padded channels: 76 f32x2 pairs
#define TPX  16                 // tile width
#define TPY  4                  // tile height
#define NTX  (WW / TPX)         // 16
#define NTY  (HH / TPY)         // 64
#define NTILES (NTX * NTY)      // 1024
#define QPAIR 19                // f32x2 pairs per quarter-thread
#define CHUNK 16                // gaussians staged per chunk
#define TRB  150                // transpose blocks (150*256*4 = 153600)
#define CULLB (NTILES / 8)      // 128 cull blocks (8 tiles each)
#define RGRID 444               // persistent render CTAs (148 SM x 3)

// Scratch (device globals; no allocation allowed)
__device__ float g_params[NG * 8];                 // cx, cy, c1, c2, c3, op
__device__ __align__(16) float g_featT[NG * NCHF]; // [n][152] channel-major
__device__ short g_list[NTILES][NG];               // per-tile ordered lists
__device__ int   g_count[NTILES];
__device__ int   g_ticket;                         // dynamic tile ticket

// ---------------------------------------------------------------------------
__device__ __forceinline__ void project(int n,
        const float* __restrict__ xyz, const float* __restrict__ chol,
        const float* __restrict__ opac,
        float& cx, float& cy, float& c1, float& c2, float& c3, float& op,
        float4& bb) {
    float2 xr = ((const float2*)xyz)[n];
    float x  = tanhf(xr.x);
    float y  = tanhf(xr.y);
    float l1 = chol[3 * n + 0] + 0.5f;
    float l2 = chol[3 * n + 1];
    float l3 = chol[3 * n + 2] + 0.5f;
    float a = l1 * l1;
    float b = l1 * l2;
    float c = l2 * l2 + l3 * l3;
    float det = a * c - b * b;
    c1 = c / det;
    c2 = -b / det;
    c3 = a / det;
    cx = 0.5f * ((x + 1.0f) * (float)WW - 1.0f);
    cy = 0.5f * ((y + 1.0f) * (float)HH - 1.0f);
    op = opac[n];
    // alpha >= 1/255 <=> sigma <= T = ln(255*op); ellipse extents + margin
    float T = __logf(255.0f * op);
    if (T > 0.0f) {
        float hx = sqrtf(2.0f * T * a) + 2.0f;
        float hy = sqrtf(2.0f * T * c) + 2.0f;
        bb = make_float4(cx - hx, cx + hx, cy - hy, cy + hy);
    } else {
        bb = make_float4(1e9f, -1e9f, 1e9f, -1e9f);
    }
}

// ---------------------------------------------------------------------------
// Kernel A: blocks [0,150)  feature transpose, 4 elems/thread (MLP=4);
//           blocks [150,278) project-in-SMEM + warp-per-tile cull;
//           cull block 0 persists params, zeroes padding, resets ticket.
// ---------------------------------------------------------------------------
__global__ void prep_and_cull(const float* __restrict__ xyz,
                              const float* __restrict__ chol,
                              const float* __restrict__ opac,
                              const float* __restrict__ fdc,
                              const int*   __restrict__ cid_p) {
    const int tid = threadIdx.x;
    if (blockIdx.x < TRB) {
        const int cid = *cid_p;
#pragma unroll
        for (int k = 0; k < 4; k++) {
            int i = blockIdx.x * 1024 + k * 256 + tid;   // (t,n), n minor
            int t = i >> 10;                             // channel 0..149
            int n = i & (NG - 1);
            int m  = t / 3;
            int cc = t - 3 * m;
            float v = fdc[(((size_t)cid * MM + m) * NG + n) * 3 + cc];
            g_featT[n * NCHF + t] = v;
        }
        return;
    }

    __shared__ __align__(16) float4 s_bb[NG];            // 16 KB
    const int cb = blockIdx.x - TRB;                     // 0..127
#pragma unroll
    for (int j = 0; j < 4; j++) {
        int n = tid + j * 256;
        float cx, cy, c1, c2, c3, op;
        float4 bb;
        project(n, xyz, chol, opac, cx, cy, c1, c2, c3, op, bb);
        s_bb[n] = bb;
        if (cb == 0) {
            float4* p = (float4*)&g_params[n * 8];
            p[0] = make_float4(cx, cy, c1, c2);
            p[1] = make_float4(c3, op, 0.0f, 0.0f);
            g_featT[n * NCHF + NCH]     = 0.0f;          // zero 2 pad channels
            g_featT[n * NCHF + NCH + 1] = 0.0f;
        }
    }
    if (cb == 0 && tid == 0) g_ticket = 0;               // reset dynamic ticket
    __syncthreads();

    const int lane = tid & 31;
    const int tile = cb * 8 + (tid >> 5);                // one warp per tile
    const float fxl = (float)((tile & (NTX - 1)) * TPX);
    const float fxh = fxl + (float)(TPX - 1);
    const float fyl = (float)((tile >> 4) * TPY);
    const float fyh = fyl + (float)(TPY - 1);
    int off = 0;
#pragma unroll 8
    for (int j = 0; j < NG / 32; j++) {
        int g = j * 32 + lane;
        float4 bb = s_bb[g];
        bool hit = (bb.x <= fxh) && (bb.y >= fxl) && (bb.z <= fyh) && (bb.w >= fyl);
        unsigned m = __ballot_sync(0xffffffffu, hit);
        if (hit) {
            int rank = __popc(m & ((1u << lane) - 1u));
            g_list[tile][off + rank] = (short)g;
        }
        off += __popc(m);
    }
    if (lane == 0) g_count[tile] = off;
}

// ---------------------------------------------------------------------------
// Kernel B: persistent render. CTAs pull tiles from a dynamic ticket.
// Per tile: 16x4 px, 4 threads/pixel (warp-uniform quarter), SMEM-staged.
// ---------------------------------------------------------------------------
__global__ __launch_bounds__(256, 3) void render(float* __restrict__ out) {
    __shared__ __align__(16) float4 s_feat[CHUNK][NCHF / 4];  // 9.5 KB
    __shared__ float s_cp[CHUNK][6];
    __shared__ int   s_tile;

    const int tid = threadIdx.x;
    const int pix = tid & 63;              // 0..63
    const int q   = tid >> 6;              // channel quarter, warp-uniform

    for (;;) {
        if (tid == 0) s_tile = atomicAdd(&g_ticket, 1);
        __syncthreads();
        const int tile = s_tile;
        if (tile >= NTILES) return;

        const int tx0 = (tile & (NTX - 1)) * TPX;
        const int ty0 = (tile >> 4) * TPY;
        const float fx = (float)(tx0 + (pix & (TPX - 1)));
        const float fy = (float)(ty0 + (pix >> 4));
        const int count = g_count[tile];
        const short* __restrict__ list = g_list[tile];

        unsigned long long acc[QPAIR];
#pragma unroll
        for (int k = 0; k < QPAIR; k++) acc[k] = 0ull;

        for (int c0 = 0; c0 < count; c0 += CHUNK) {
            int nc = min(CHUNK, count - c0);
            for (int i = tid; i < nc * (NCHF / 4); i += 256) {
                int g = i / (NCHF / 4);
                int k = i - g * (NCHF / 4);
                s_feat[g][k] = ((const float4*)g_featT)[(int)list[c0 + g] * (NCHF / 4) + k];
            }
            if (tid < nc * 6) {
                int g = tid / 6;
                int k = tid - g * 6;
                s_cp[g][k] = g_params[(int)list[c0 + g] * 8 + k];
            }
            __syncthreads();

            for (int g = 0; g < nc; g++) {
                float cx = s_cp[g][0], cy = s_cp[g][1];
                float c1 = s_cp[g][2], c2 = s_cp[g][3], c3 = s_cp[g][4];
                float op = s_cp[g][5];
                float dx = cx - fx;
                float dy = cy - fy;
                float sig = 0.5f * (c1 * dx * dx + c3 * dy * dy) + c2 * dx * dy;
                float al = fminf(0.999f, op * __expf(-sig));
                al = (sig >= 0.0f && al >= (1.0f / 255.0f)) ? al : 0.0f;
                if (__ballot_sync(0xffffffffu, al > 0.0f) == 0u) continue;
                unsigned long long ap;
                asm("mov.b64 %0, {%1,%1};" : "=l"(ap) : "r"(__float_as_uint(al)));
                // this quarter's 19 pairs (38 floats), broadcast LDS
                const unsigned long long* fp =
                    (const unsigned long long*)((const float*)&s_feat[g][0] + q * (2 * QPAIR));
#pragma unroll
                for (int k = 0; k < QPAIR; k++) {
                    unsigned long long f2 = fp[k];
                    asm("fma.rn.f32x2 %0, %1, %2, %0;" : "+l"(acc[k]) : "l"(ap), "l"(f2));
                }
            }
            __syncthreads();
        }

        // ---- epilogue: coalesced channel-plane stores ----
        const int pofs = (ty0 + (pix >> 4)) * WW + tx0 + (pix & (TPX - 1));
#pragma unroll
        for (int k = 0; k < QPAIR; k++) {
            int kp = q * QPAIR + k;          // global pair index
            if (kp < NCH / 2) {              // pair 75 is padding
                unsigned lo, hi;
                asm("mov.b64 {%0,%1}, %2;" : "=r"(lo), "=r"(hi) : "l"(acc[k]));
                out[(size_t)(2 * kp)     * NP + pofs] = __uint_as_float(lo);
                out[(size_t)(2 * kp + 1) * NP + pofs] = __uint_as_float(hi);
            }
        }
        __syncthreads();   // protect s_tile/s_feat before next iteration
    }
}

// ---------------------------------------------------------------------------
extern "C" void kernel_launch(void* const* d_in, const int* in_sizes, int n_in,
                              void* d_out, int out_size) {
    const float* xyz  = (const float*)d_in[0];  // [N,2]
    const float* chol = (const float*)d_in[1];  // [N,3]
    const float* opac = (const float*)d_in[2];  // [N,1]
    const float* fdc  = (const float*)d_in[3];  // [K,M,N,3]
    const int*   cid  = (const int*)d_in[4];    // scalar

    prep_and_cull<<<TRB + CULLB, 256>>>(xyz, chol, opac, fdc, cid);
    render<<<RGRID, 256>>>((float*)d_out);
}